// round 10
// baseline (speedup 1.0000x reference)
#include <cuda_runtime.h>
#include <cstdint>

// VersatileConvSE3  E=16384, C=O=32, D=S=16, F=44, M=32
#define E_TOT 16384
#define NE    32
#define NTHR  512
#define NBLK  (E_TOT / NE)

typedef unsigned long long u64;
#define FMA2(d,a,b,c) asm("fma.rn.f32x2 %0, %1, %2, %3;" : "=l"(d) : "l"(a), "l"(b), "l"(c))
__device__ __forceinline__ u64 pk2(float a, float b) {
    u64 r; asm("mov.b64 %0, {%1, %2};" : "=l"(r) : "f"(a), "f"(b)); return r;
}

__device__ float g_HT[32 * E_TOT];   // h transposed: [m][e]

__device__ __forceinline__ float warp_sum(float v) {
    v += __shfl_xor_sync(0xffffffffu, v, 16);
    v += __shfl_xor_sync(0xffffffffu, v, 8);
    v += __shfl_xor_sync(0xffffffffu, v, 4);
    v += __shfl_xor_sync(0xffffffffu, v, 2);
    v += __shfl_xor_sync(0xffffffffu, v, 1);
    return v;
}

__global__ __launch_bounds__(256) void mlp_kernel(
    const float* __restrict__ inv,
    const float* __restrict__ w1, const float* __restrict__ b1,
    const float* __restrict__ g1, const float* __restrict__ be1,
    const float* __restrict__ w2, const float* __restrict__ b2,
    const float* __restrict__ g2, const float* __restrict__ be2)
{
    const int e = blockIdx.x * 8 + (threadIdx.x >> 5);
    const int lane = threadIdx.x & 31;
    const float* x = inv + e * 16;
    float y = b1[lane];
    #pragma unroll
    for (int d = 0; d < 16; ++d) y += x[d] * w1[lane * 16 + d];
    float mu  = warp_sum(y) * (1.0f/32.0f);
    float dz  = y - mu;
    float var = warp_sum(dz*dz) * (1.0f/32.0f);
    float h1  = fmaxf(dz * rsqrtf(var + 1e-5f) * g1[lane] + be1[lane], 0.0f);
    float y2 = b2[lane];
    #pragma unroll
    for (int m = 0; m < 32; ++m)
        y2 += __shfl_sync(0xffffffffu, h1, m) * w2[lane * 32 + m];
    mu  = warp_sum(y2) * (1.0f/32.0f);
    dz  = y2 - mu;
    var = warp_sum(dz*dz) * (1.0f/32.0f);
    g_HT[(size_t)lane * E_TOT + e] = fmaxf(dz * rsqrtf(var + 1e-5f) * g2[lane] + be2[lane], 0.0f);
}

// smem float offsets
#define OF_T   0         // [c32] c-stride 640, e-stride 20 -> 20480
#define OF_W3  20480     // [512 rows][36]                  -> 18432
#define OF_RW  38912     // [512 rows][36]; bas aliased (e-stride 260, 8320 used)
#define SMEM_FLOATS 57344   // 229376 bytes

__global__ __launch_bounds__(NTHR, 1) void conv_kernel(
    const float* __restrict__ feat,
    const float* __restrict__ basis,
    const float* __restrict__ w3,
    float* __restrict__ out)
{
    extern __shared__ __align__(16) float sm[];
    const int tid = threadIdx.x;
    const int e0  = blockIdx.x * NE;

    const int le  = tid & 31;               // e lane (Tgen / B / bas / store)
    const int cp  = tid >> 5;               // Tgen c-pair; bas d
    const int s_r = tid >> 3, s_k = tid & 7;   // w3 stager
    const int a_la = tid & 127, a_eo = tid >> 7;   // A: 4 rows x 8 e
    const int b_oq = (tid >> 5) & 3, b_sq = tid >> 7;  // B: 4 o x 4 s

    // feat -> regs: rows c = 2cp, 2cp+1 of edge le
    float fr0[16], fr1[16];
    {
        const float4* fa = (const float4*)(feat + ((size_t)(e0 + le) * 32 + cp * 2) * 16);
        #pragma unroll
        for (int i = 0; i < 4; ++i) {
            float4 v = __ldg(fa + i);
            fr0[4*i] = v.x; fr0[4*i+1] = v.y; fr0[4*i+2] = v.z; fr0[4*i+3] = v.w;
            float4 w = __ldg(fa + 4 + i);
            fr1[4*i] = w.x; fr1[4*i+1] = w.y; fr1[4*i+2] = w.z; fr1[4*i+3] = w.w;
        }
    }

    // bas prefetch (f=0): row (e=le, d=cp), 16 floats
    const float* bas_base = basis + (((size_t)(e0 + le) * 16 + cp) * 44) * 16;
    float4 bp[4];
    #pragma unroll
    for (int k = 0; k < 4; ++k) bp[k] = __ldg((const float4*)bas_base + k);

    const float* hbase = g_HT + e0 + a_eo * 8;

    u64 acc[2][4][2];
    #pragma unroll
    for (int i = 0; i < 2; ++i)
        #pragma unroll
        for (int j = 0; j < 4; ++j) { acc[i][j][0] = 0ull; acc[i][j][1] = 0ull; }

    // Phase A: rows la+128i (i<4) x 8 e, 32 m. h via broadcast LDG from g_HT.
    #define A_BODY()                                                              \
    {                                                                             \
        u64 A_[4][4];                                                             \
        _Pragma("unroll")                                                         \
        for (int i = 0; i < 4; ++i) { A_[i][0]=0ull; A_[i][1]=0ull; A_[i][2]=0ull; A_[i][3]=0ull; } \
        const float* wb = sm + OF_W3 + a_la * 36;                                 \
        _Pragma("unroll")                                                         \
        for (int mq = 0; mq < 8; ++mq) {                                          \
            float4 wq[4];                                                         \
            _Pragma("unroll")                                                     \
            for (int i = 0; i < 4; ++i) wq[i] = *(const float4*)(wb + i * (128*36) + mq * 4); \
            _Pragma("unroll")                                                     \
            for (int mm = 0; mm < 4; ++mm) {                                      \
                const int m = mq * 4 + mm;                                        \
                const ulonglong2* hp = (const ulonglong2*)(hbase + (size_t)m * E_TOT); \
                ulonglong2 ha = __ldg(hp), hc = __ldg(hp + 1);                    \
                const float w0 = (mm==0)?wq[0].x:(mm==1)?wq[0].y:(mm==2)?wq[0].z:wq[0].w; \
                const float w1v= (mm==0)?wq[1].x:(mm==1)?wq[1].y:(mm==2)?wq[1].z:wq[1].w; \
                const float w2v= (mm==0)?wq[2].x:(mm==1)?wq[2].y:(mm==2)?wq[2].z:wq[2].w; \
                const float w3v= (mm==0)?wq[3].x:(mm==1)?wq[3].y:(mm==2)?wq[3].z:wq[3].w; \
                u64 p;                                                            \
                p = pk2(w0, w0);                                                  \
                FMA2(A_[0][0], p, ha.x, A_[0][0]); FMA2(A_[0][1], p, ha.y, A_[0][1]); \
                FMA2(A_[0][2], p, hc.x, A_[0][2]); FMA2(A_[0][3], p, hc.y, A_[0][3]); \
                p = pk2(w1v, w1v);                                                \
                FMA2(A_[1][0], p, ha.x, A_[1][0]); FMA2(A_[1][1], p, ha.y, A_[1][1]); \
                FMA2(A_[1][2], p, hc.x, A_[1][2]); FMA2(A_[1][3], p, hc.y, A_[1][3]); \
                p = pk2(w2v, w2v);                                                \
                FMA2(A_[2][0], p, ha.x, A_[2][0]); FMA2(A_[2][1], p, ha.y, A_[2][1]); \
                FMA2(A_[2][2], p, hc.x, A_[2][2]); FMA2(A_[2][3], p, hc.y, A_[2][3]); \
                p = pk2(w3v, w3v);                                                \
                FMA2(A_[3][0], p, ha.x, A_[3][0]); FMA2(A_[3][1], p, ha.y, A_[3][1]); \
                FMA2(A_[3][2], p, hc.x, A_[3][2]); FMA2(A_[3][3], p, hc.y, A_[3][3]); \
            }                                                                     \
        }                                                                         \
        _Pragma("unroll")                                                         \
        for (int i = 0; i < 4; ++i) {                                             \
            float* dp = sm + OF_RW + (size_t)(a_la + 128 * i) * 36 + a_eo * 8;    \
            ulonglong2 v;                                                         \
            v.x = A_[i][0]; v.y = A_[i][1]; ((ulonglong2*)dp)[0] = v;             \
            v.x = A_[i][2]; v.y = A_[i][3]; ((ulonglong2*)(dp + 4))[0] = v;       \
        }                                                                         \
    }

    // Phase B: acc[oh][j][4s] += rw[(oq*4+j)*32+c][e] * T[c][e][4s]
    #define B_BODY(OH)                                                            \
    {                                                                             \
        const float* rwb = sm + OF_RW + le;                                       \
        const float* tb  = sm + OF_T + le * 20 + b_sq * 4;                        \
        _Pragma("unroll")                                                         \
        for (int c = 0; c < 32; ++c) {                                            \
            ulonglong2 q = *(const ulonglong2*)(tb + c * 640);                    \
            _Pragma("unroll")                                                     \
            for (int j = 0; j < 4; ++j) {                                         \
                float rv = rwb[(size_t)((b_oq * 4 + j) * 32 + c) * 36];           \
                u64 rp = pk2(rv, rv);                                             \
                FMA2(acc[OH][j][0], rp, q.x, acc[OH][j][0]);                      \
                FMA2(acc[OH][j][1], rp, q.y, acc[OH][j][1]);                      \
            }                                                                     \
        }                                                                         \
    }

    for (int f = 0; f < 44; ++f) {
        __syncthreads();   // S0: prior B(h1) done reading rw -> bas region free
        {
            float4* bd = (float4*)(sm + OF_RW + le * 260 + cp * 16);
            bd[0] = bp[0]; bd[1] = bp[1]; bd[2] = bp[2]; bd[3] = bp[3];
        }
        __syncthreads();   // S1: bas ready; T/w3 of f-1 consumed
        if (f < 43) {
            const float4* nb = (const float4*)(bas_base + (size_t)(f + 1) * 16);
            bp[0] = __ldg(nb); bp[1] = __ldg(nb + 1);
            bp[2] = __ldg(nb + 2); bp[3] = __ldg(nb + 3);
        }

        // T-gen: T[2cp..2cp+1][le][16s] = sum_d feat * bas
        {
            u64 t0[8], t1[8];
            #pragma unroll
            for (int k = 0; k < 8; ++k) { t0[k] = 0ull; t1[k] = 0ull; }
            const float* bb = sm + OF_RW + le * 260;
            #pragma unroll
            for (int d = 0; d < 16; ++d) {
                const ulonglong2* q = (const ulonglong2*)(bb + d * 16);
                ulonglong2 qa = q[0], qb = q[1], qc = q[2], qd = q[3];
                u64 fa = pk2(fr0[d], fr0[d]);
                u64 fb = pk2(fr1[d], fr1[d]);
                FMA2(t0[0], fa, qa.x, t0[0]); FMA2(t0[1], fa, qa.y, t0[1]);
                FMA2(t0[2], fa, qb.x, t0[2]); FMA2(t0[3], fa, qb.y, t0[3]);
                FMA2(t0[4], fa, qc.x, t0[4]); FMA2(t0[5], fa, qc.y, t0[5]);
                FMA2(t0[6], fa, qd.x, t0[6]); FMA2(t0[7], fa, qd.y, t0[7]);
                FMA2(t1[0], fb, qa.x, t1[0]); FMA2(t1[1], fb, qa.y, t1[1]);
                FMA2(t1[2], fb, qb.x, t1[2]); FMA2(t1[3], fb, qb.y, t1[3]);
                FMA2(t1[4], fb, qc.x, t1[4]); FMA2(t1[5], fb, qc.y, t1[5]);
                FMA2(t1[6], fb, qd.x, t1[6]); FMA2(t1[7], fb, qd.y, t1[7]);
            }
            float* ta = sm + OF_T + (size_t)(cp * 2) * 640 + le * 20;
            ulonglong2 v;
            #pragma unroll
            for (int k = 0; k < 4; ++k) {
                v.x = t0[2*k]; v.y = t0[2*k+1]; ((ulonglong2*)(ta + 4*k))[0] = v;
            }
            #pragma unroll
            for (int k = 0; k < 4; ++k) {
                v.x = t1[2*k]; v.y = t1[2*k+1]; ((ulonglong2*)(ta + 640 + 4*k))[0] = v;
            }
        }

        // w3 half-0: LDG + STS
        {
            float4 w_[8];
            #pragma unroll
            for (int i = 0; i < 8; ++i) {
                const int r = i * 64 + s_r;
                const int o = r >> 5, c = r & 31;
                w_[i] = __ldg((const float4*)(w3 + ((size_t)o * 1408 + (size_t)c * 44 + f) * 32 + s_k * 4));
            }
            #pragma unroll
            for (int i = 0; i < 8; ++i)
                *(float4*)(sm + OF_W3 + (i * 64 + s_r) * 36 + s_k * 4) = w_[i];
        }
        __syncthreads();   // S2: T + w3(h0) ready; bas reads done

        A_BODY();          // rw(h0); overwrites bas region (safe)
        __syncthreads();   // S3: rw(h0) ready; w3 buffer free

        // w3 half-1 LDG+STS, then B(h0)
        {
            float4 w_[8];
            #pragma unroll
            for (int i = 0; i < 8; ++i) {
                const int r = 512 + i * 64 + s_r;
                const int o = r >> 5, c = r & 31;
                w_[i] = __ldg((const float4*)(w3 + ((size_t)o * 1408 + (size_t)c * 44 + f) * 32 + s_k * 4));
            }
            #pragma unroll
            for (int i = 0; i < 8; ++i)
                *(float4*)(sm + OF_W3 + (i * 64 + s_r) * 36 + s_k * 4) = w_[i];
        }
        B_BODY(0);
        __syncthreads();   // S4: w3(h1) ready AND B(h0) done reading rw

        A_BODY();          // rw(h1) overwrites rw(h0)
        __syncthreads();   // S5: rw(h1) ready

        B_BODY(1);
    }

    // store: thread owns (e=le, o = oh*16 + oq*4 + j, s = sq*4..+4)
    #pragma unroll
    for (int oh = 0; oh < 2; ++oh)
        #pragma unroll
        for (int j = 0; j < 4; ++j) {
            const int o = oh * 16 + b_oq * 4 + j;
            float* op = out + ((size_t)(e0 + le) * 32 + o) * 16 + b_sq * 4;
            ulonglong2 v; v.x = acc[oh][j][0]; v.y = acc[oh][j][1];
            *(ulonglong2*)op = v;
        }
    #undef A_BODY
    #undef B_BODY
}

extern "C" void kernel_launch(void* const* d_in, const int* in_sizes, int n_in,
                              void* d_out, int out_size)
{
    const float* features = (const float*)d_in[0];
    const float* inv      = (const float*)d_in[1];
    const float* basis    = (const float*)d_in[2];
    const float* w1  = (const float*)d_in[3];
    const float* b1  = (const float*)d_in[4];
    const float* g1  = (const float*)d_in[5];
    const float* be1 = (const float*)d_in[6];
    const float* w2  = (const float*)d_in[7];
    const float* b2  = (const float*)d_in[8];
    const float* g2  = (const float*)d_in[9];
    const float* be2 = (const float*)d_in[10];
    const float* w3  = (const float*)d_in[11];
    float* out = (float*)d_out;

    cudaFuncSetAttribute(conv_kernel, cudaFuncAttributeMaxDynamicSharedMemorySize,
                         SMEM_FLOATS * (int)sizeof(float));

    mlp_kernel<<<E_TOT / 8, 256>>>(inv, w1, b1, g1, be1, w2, b2, g2, be2);
    conv_kernel<<<NBLK, NTHR, SMEM_FLOATS * sizeof(float)>>>(features, basis, w3, out);
}

// round 11
// speedup vs baseline: 1.1790x; 1.1790x over previous
#include <cuda_runtime.h>
#include <cstdint>

// VersatileConvSE3  E=16384, C=O=32, D=S=16, F=44, M=32
#define E_TOT 16384
#define NE    16
#define NTHR  512
#define NBLK  (E_TOT / NE)

typedef unsigned long long u64;
#define FMA2(d,a,b,c) asm("fma.rn.f32x2 %0, %1, %2, %3;" : "=l"(d) : "l"(a), "l"(b), "l"(c))
__device__ __forceinline__ u64 pk2(float a, float b) {
    u64 r; asm("mov.b64 %0, {%1, %2};" : "=l"(r) : "f"(a), "f"(b)); return r;
}
__device__ __forceinline__ float2 upk2(u64 v) {
    float a, b; asm("mov.b64 {%0, %1}, %2;" : "=f"(a), "=f"(b) : "l"(v));
    return make_float2(a, b);
}

__device__ float g_H[E_TOT * 32];

__device__ __forceinline__ float warp_sum(float v) {
    v += __shfl_xor_sync(0xffffffffu, v, 16);
    v += __shfl_xor_sync(0xffffffffu, v, 8);
    v += __shfl_xor_sync(0xffffffffu, v, 4);
    v += __shfl_xor_sync(0xffffffffu, v, 2);
    v += __shfl_xor_sync(0xffffffffu, v, 1);
    return v;
}

__global__ __launch_bounds__(256) void mlp_kernel(
    const float* __restrict__ inv,
    const float* __restrict__ w1, const float* __restrict__ b1,
    const float* __restrict__ g1, const float* __restrict__ be1,
    const float* __restrict__ w2, const float* __restrict__ b2,
    const float* __restrict__ g2, const float* __restrict__ be2)
{
    const int e = blockIdx.x * 8 + (threadIdx.x >> 5);
    const int lane = threadIdx.x & 31;
    const float* x = inv + e * 16;
    float y = b1[lane];
    #pragma unroll
    for (int d = 0; d < 16; ++d) y += x[d] * w1[lane * 16 + d];
    float mu  = warp_sum(y) * (1.0f/32.0f);
    float dz  = y - mu;
    float var = warp_sum(dz*dz) * (1.0f/32.0f);
    float h1  = fmaxf(dz * rsqrtf(var + 1e-5f) * g1[lane] + be1[lane], 0.0f);
    float y2 = b2[lane];
    #pragma unroll
    for (int m = 0; m < 32; ++m)
        y2 += __shfl_sync(0xffffffffu, h1, m) * w2[lane * 32 + m];
    mu  = warp_sum(y2) * (1.0f/32.0f);
    dz  = y2 - mu;
    var = warp_sum(dz*dz) * (1.0f/32.0f);
    g_H[e * 32 + lane] = fmaxf(dz * rsqrtf(var + 1e-5f) * g2[lane] + be2[lane], 0.0f);
}

// smem float offsets
#define OF_H    0        // [e16][m32]                  512
#define OF_BAS  512      // [e16][d16][s16]             4096
#define OF_T    4608     // [c32] str 324, e str 20     10368
#define OF_RW   14976    // [row1024][20]               20480
#define OF_W3   35456    // [lrow512][36]               18432
#define SMEM_FLOATS 53888   // 215552 bytes
#define T_CS 324

__global__ __launch_bounds__(NTHR, 1) void conv_kernel(
    const float* __restrict__ feat,
    const float* __restrict__ basis,
    const float* __restrict__ w3,
    float* __restrict__ out)
{
    extern __shared__ __align__(16) float sm[];
    const int tid = threadIdx.x;
    const int e0  = blockIdx.x * NE;

    // roles
    const int tg_e = tid >> 5, tg_c = tid & 31;          // T-gen
    const int s_r  = tid >> 3, s_k = tid & 7;            // w3 stager
    const int a_eq = tid & 3,  a_rg = tid >> 2;          // Phase A: 4 rows x 4 e, m-pairs
    const int b_e  = tid & 15;                           // Phase B
    const int b_og = (tid >> 4) & 15, b_sh = tid >> 8;
    const int b_o0 = b_og * 2, b_o1 = b_o0 + 1;

    // stage H as [e][m] (coalesced copy)
    sm[OF_H + tid] = g_H[(size_t)e0 * 32 + tid];

    // feat -> regs
    float fr[16];
    {
        const float4* fp = (const float4*)(feat + ((size_t)(e0 + tg_e) * 32 + tg_c) * 16);
        #pragma unroll
        for (int i = 0; i < 4; ++i) {
            float4 v = __ldg(fp + i);
            fr[4*i] = v.x; fr[4*i+1] = v.y; fr[4*i+2] = v.z; fr[4*i+3] = v.w;
        }
    }

    // basis prefetch (f=0)
    const float* bas_base = basis + (((size_t)(e0 + (tid >> 5)) * 16 + ((tid >> 1) & 15)) * 44) * 16 + (tid & 1) * 8;
    float4 bpre0 = __ldg((const float4*)bas_base);
    float4 bpre1 = __ldg((const float4*)bas_base + 1);

    // Phase B persistent accumulators: 2 o x 8 s
    u64 acc0[4], acc1[4];
    #pragma unroll
    for (int k = 0; k < 4; ++k) { acc0[k] = 0ull; acc1[k] = 0ull; }

    __syncthreads();

    // Phase A: 4 rows (rg+128i) x 4 e (eq*4+e'), accumulate over m-pairs.
    // w and h both loaded as packed u64 pairs -> no pk2 in the loop.
    #define PHASE_A(HALF)                                                         \
    {                                                                             \
        u64 A_[4][4];                                                             \
        _Pragma("unroll")                                                         \
        for (int i = 0; i < 4; ++i) { A_[i][0]=0ull; A_[i][1]=0ull; A_[i][2]=0ull; A_[i][3]=0ull; } \
        const float* wb = sm + OF_W3 + a_rg * 36;                                 \
        const float* hb = sm + OF_H + a_eq * 4 * 32;                              \
        _Pragma("unroll")                                                         \
        for (int mq = 0; mq < 8; ++mq) {                                          \
            ulonglong2 wv[4], hv[4];                                              \
            _Pragma("unroll")                                                     \
            for (int i = 0; i < 4; ++i) wv[i] = *(const ulonglong2*)(wb + i * (128*36) + mq * 4); \
            _Pragma("unroll")                                                     \
            for (int e = 0; e < 4; ++e) hv[e] = *(const ulonglong2*)(hb + e * 32 + mq * 4); \
            _Pragma("unroll")                                                     \
            for (int i = 0; i < 4; ++i) {                                         \
                _Pragma("unroll")                                                 \
                for (int e = 0; e < 4; ++e) {                                     \
                    FMA2(A_[i][e], wv[i].x, hv[e].x, A_[i][e]);                   \
                    FMA2(A_[i][e], wv[i].y, hv[e].y, A_[i][e]);                   \
                }                                                                 \
            }                                                                     \
        }                                                                         \
        _Pragma("unroll")                                                         \
        for (int i = 0; i < 4; ++i) {                                             \
            float2 v0 = upk2(A_[i][0]), v1 = upk2(A_[i][1]);                      \
            float2 v2 = upk2(A_[i][2]), v3 = upk2(A_[i][3]);                      \
            ulonglong2 st;                                                        \
            st.x = pk2(v0.x + v0.y, v1.x + v1.y);                                 \
            st.y = pk2(v2.x + v2.y, v3.x + v3.y);                                 \
            float* dp = sm + OF_RW + (size_t)((HALF)*512 + a_rg + 128*i) * 20 + a_eq * 4; \
            *(ulonglong2*)dp = st;                                                \
        }                                                                         \
    }

    for (int f = 0; f < 44; ++f) {
        // stage basis slice
        {
            float4* bp = (float4*)(sm + OF_BAS + tid * 8);
            bp[0] = bpre0; bp[1] = bpre1;
        }
        __syncthreads();   // S1
        if (f < 43) {
            const float* bs = bas_base + (size_t)(f + 1) * 16;
            bpre0 = __ldg((const float4*)bs);
            bpre1 = __ldg((const float4*)bs + 1);
        }

        // w3 half-0 LDG (overlapped by T-gen)
        float4 w_[8];
        #pragma unroll
        for (int i = 0; i < 8; ++i) {
            const int lr = i * 64 + s_r;
            const int o = lr >> 5, c = lr & 31;
            w_[i] = __ldg((const float4*)(w3 + ((size_t)o * 1408 + (size_t)c * 44 + f) * 32 + s_k * 4));
        }

        // T-gen: T[c][e][s] = sum_d feat*bas
        {
            u64 t[8];
            #pragma unroll
            for (int k = 0; k < 8; ++k) t[k] = 0ull;
            const char* bb = (const char*)(sm + OF_BAS + tg_e * 256);
            #pragma unroll
            for (int d = 0; d < 16; ++d) {
                u64 fp2 = pk2(fr[d], fr[d]);
                const ulonglong2* bp = (const ulonglong2*)(bb + d * 64);
                ulonglong2 q0 = bp[0], q1 = bp[1], q2 = bp[2], q3 = bp[3];
                FMA2(t[0], fp2, q0.x, t[0]); FMA2(t[1], fp2, q0.y, t[1]);
                FMA2(t[2], fp2, q1.x, t[2]); FMA2(t[3], fp2, q1.y, t[3]);
                FMA2(t[4], fp2, q2.x, t[4]); FMA2(t[5], fp2, q2.y, t[5]);
                FMA2(t[6], fp2, q3.x, t[6]); FMA2(t[7], fp2, q3.y, t[7]);
            }
            ulonglong2* tp = (ulonglong2*)(sm + OF_T + tg_c * T_CS + tg_e * 20);
            #pragma unroll
            for (int k = 0; k < 4; ++k) { ulonglong2 v; v.x = t[2*k]; v.y = t[2*k+1]; tp[k] = v; }
        }

        #pragma unroll
        for (int i = 0; i < 8; ++i) {
            const int lr = i * 64 + s_r;
            *(float4*)(sm + OF_W3 + lr * 36 + s_k * 4) = w_[i];
        }
        __syncthreads();   // S2: sW3 half0 + sT ready

        // prefetch half-1 w3 into regs (hidden behind A half0)
        float4 wn_[8];
        #pragma unroll
        for (int i = 0; i < 8; ++i) {
            const int gr = 512 + i * 64 + s_r;
            const int o = gr >> 5, c = gr & 31;
            wn_[i] = __ldg((const float4*)(w3 + ((size_t)o * 1408 + (size_t)c * 44 + f) * 32 + s_k * 4));
        }

        PHASE_A(0)
        __syncthreads();   // S3: rw half0 done, sW3 free

        #pragma unroll
        for (int i = 0; i < 8; ++i) {
            const int lr = i * 64 + s_r;
            *(float4*)(sm + OF_W3 + lr * 36 + s_k * 4) = wn_[i];
        }
        __syncthreads();   // S4: sW3 half1 ready

        PHASE_A(1)
        __syncthreads();   // S5: all rw ready

        // Phase B: acc[e][2o][8s] += rw[o*32+c][e] * T[c][e][8s], full c
        {
            const float* rwb = sm + OF_RW + b_e;
            const char* tb = (const char*)(sm + OF_T + b_e * 20 + b_sh * 8);
            #pragma unroll
            for (int c = 0; c < 32; ++c) {
                float rv0 = rwb[(b_o0 * 32 + c) * 20];
                float rv1 = rwb[(b_o1 * 32 + c) * 20];
                const ulonglong2* tp = (const ulonglong2*)(tb + c * (T_CS * 4));
                ulonglong2 qa = tp[0], qb = tp[1];
                u64 rp0 = pk2(rv0, rv0), rp1 = pk2(rv1, rv1);
                FMA2(acc0[0], rp0, qa.x, acc0[0]); FMA2(acc0[1], rp0, qa.y, acc0[1]);
                FMA2(acc0[2], rp0, qb.x, acc0[2]); FMA2(acc0[3], rp0, qb.y, acc0[3]);
                FMA2(acc1[0], rp1, qa.x, acc1[0]); FMA2(acc1[1], rp1, qa.y, acc1[1]);
                FMA2(acc1[2], rp1, qb.x, acc1[2]); FMA2(acc1[3], rp1, qb.y, acc1[3]);
            }
        }
    }

    // direct store: thread owns (e, o0/o1, 8 s at b_sh*8)
    {
        float* op0 = out + (((size_t)(e0 + b_e) * 32) + b_o0) * 16 + b_sh * 8;
        float* op1 = out + (((size_t)(e0 + b_e) * 32) + b_o1) * 16 + b_sh * 8;
        ulonglong2 v;
        v.x = acc0[0]; v.y = acc0[1]; ((ulonglong2*)op0)[0] = v;
        v.x = acc0[2]; v.y = acc0[3]; ((ulonglong2*)op0)[1] = v;
        v.x = acc1[0]; v.y = acc1[1]; ((ulonglong2*)op1)[0] = v;
        v.x = acc1[2]; v.y = acc1[3]; ((ulonglong2*)op1)[1] = v;
    }
    #undef PHASE_A
}

extern "C" void kernel_launch(void* const* d_in, const int* in_sizes, int n_in,
                              void* d_out, int out_size)
{
    const float* features = (const float*)d_in[0];
    const float* inv      = (const float*)d_in[1];
    const float* basis    = (const float*)d_in[2];
    const float* w1  = (const float*)d_in[3];
    const float* b1  = (const float*)d_in[4];
    const float* g1  = (const float*)d_in[5];
    const float* be1 = (const float*)d_in[6];
    const float* w2  = (const float*)d_in[7];
    const float* b2  = (const float*)d_in[8];
    const float* g2  = (const float*)d_in[9];
    const float* be2 = (const float*)d_in[10];
    const float* w3  = (const float*)d_in[11];
    float* out = (float*)d_out;

    cudaFuncSetAttribute(conv_kernel, cudaFuncAttributeMaxDynamicSharedMemorySize,
                         SMEM_FLOATS * (int)sizeof(float));

    mlp_kernel<<<E_TOT / 8, 256>>>(inv, w1, b1, g1, be1, w2, b2, g2, be2);
    conv_kernel<<<NBLK, NTHR, SMEM_FLOATS * sizeof(float)>>>(features, basis, w3, out);
}

// round 12
// speedup vs baseline: 1.9413x; 1.6465x over previous
#include <cuda_runtime.h>
#include <cstdint>

// VersatileConvSE3  E=16384, C=O=32, D=S=16, F=44, M=32
#define E_TOT 16384
#define NE    16
#define NTHR  512
#define NBLK  (E_TOT / NE)

typedef unsigned long long u64;
#define FMA2(d,a,b,c) asm("fma.rn.f32x2 %0, %1, %2, %3;" : "=l"(d) : "l"(a), "l"(b), "l"(c))
__device__ __forceinline__ u64 pk2(float a, float b) {
    u64 r; asm("mov.b64 %0, {%1, %2};" : "=l"(r) : "f"(a), "f"(b)); return r;
}

__device__ float g_H[E_TOT * 32];

__device__ __forceinline__ float warp_sum(float v) {
    v += __shfl_xor_sync(0xffffffffu, v, 16);
    v += __shfl_xor_sync(0xffffffffu, v, 8);
    v += __shfl_xor_sync(0xffffffffu, v, 4);
    v += __shfl_xor_sync(0xffffffffu, v, 2);
    v += __shfl_xor_sync(0xffffffffu, v, 1);
    return v;
}

__global__ __launch_bounds__(256) void mlp_kernel(
    const float* __restrict__ inv,
    const float* __restrict__ w1, const float* __restrict__ b1,
    const float* __restrict__ g1, const float* __restrict__ be1,
    const float* __restrict__ w2, const float* __restrict__ b2,
    const float* __restrict__ g2, const float* __restrict__ be2)
{
    const int e = blockIdx.x * 8 + (threadIdx.x >> 5);
    const int lane = threadIdx.x & 31;
    const float* x = inv + e * 16;
    float y = b1[lane];
    #pragma unroll
    for (int d = 0; d < 16; ++d) y += x[d] * w1[lane * 16 + d];
    float mu  = warp_sum(y) * (1.0f/32.0f);
    float dz  = y - mu;
    float var = warp_sum(dz*dz) * (1.0f/32.0f);
    float h1  = fmaxf(dz * rsqrtf(var + 1e-5f) * g1[lane] + be1[lane], 0.0f);
    float y2 = b2[lane];
    #pragma unroll
    for (int m = 0; m < 32; ++m)
        y2 += __shfl_sync(0xffffffffu, h1, m) * w2[lane * 32 + m];
    mu  = warp_sum(y2) * (1.0f/32.0f);
    dz  = y2 - mu;
    var = warp_sum(dz*dz) * (1.0f/32.0f);
    g_H[e * 32 + lane] = fmaxf(dz * rsqrtf(var + 1e-5f) * g2[lane] + be2[lane], 0.0f);
}

// smem float offsets
#define OF_H    0        // [m32][e16]                  512
#define OF_BAS  512      // [e16][d16][s16]             4096
#define OF_T    4608     // [c32] str 324, e str 20     10368
#define OF_RW   14976    // [row1024][18]               18432
#define OF_W3   33408    // [lrow512][36]               18432
#define SMEM_FLOATS 51840
#define T_CS 324
#define T_ES 20

__global__ __launch_bounds__(NTHR, 1) void conv_kernel(
    const float* __restrict__ feat,
    const float* __restrict__ basis,
    const float* __restrict__ w3,
    float* __restrict__ out)
{
    extern __shared__ __align__(16) float sm[];
    const int tid = threadIdx.x;
    const int e0  = blockIdx.x * NE;

    // roles
    const int tg_e = tid >> 5, tg_c = tid & 31;          // T-gen
    const int s_r  = tid >> 3, s_k = tid & 7;            // w3 stager
    const int a_la = tid & 127, a_eq = tid >> 7;         // Phase A: 4 rows x 4 e (distinct!)
    const int b_e  = tid & 15;                           // Phase B
    const int b_og = (tid >> 4) & 15, b_sh = tid >> 8;
    const int b_o0 = b_og * 2, b_o1 = b_o0 + 1;

    // stage H transposed [m][e]
    sm[OF_H + (tid & 31) * 16 + (tid >> 5)] = g_H[(size_t)(e0 + (tid >> 5)) * 32 + (tid & 31)];

    // feat -> regs
    float fr[16];
    {
        const float4* fp = (const float4*)(feat + ((size_t)(e0 + tg_e) * 32 + tg_c) * 16);
        #pragma unroll
        for (int i = 0; i < 4; ++i) {
            float4 v = __ldg(fp + i);
            fr[4*i] = v.x; fr[4*i+1] = v.y; fr[4*i+2] = v.z; fr[4*i+3] = v.w;
        }
    }

    // basis prefetch (f=0)
    const float* bas_base = basis + (((size_t)(e0 + (tid >> 5)) * 16 + ((tid >> 1) & 15)) * 44) * 16 + (tid & 1) * 8;
    float4 bpre0 = __ldg((const float4*)bas_base);
    float4 bpre1 = __ldg((const float4*)bas_base + 1);

    // Phase B persistent accumulators: 2 o x 8 s
    u64 acc0[4], acc1[4];
    #pragma unroll
    for (int k = 0; k < 4; ++k) { acc0[k] = 0ull; acc1[k] = 0ull; }

    __syncthreads();

    // Phase A: 4 rows (la+128i) x 4 e (quarter a_eq), 32 m. 512 distinct work items.
    #define PHASE_A(HALF)                                                         \
    {                                                                             \
        u64 A_[4][2];                                                             \
        _Pragma("unroll")                                                         \
        for (int i = 0; i < 4; ++i) { A_[i][0] = 0ull; A_[i][1] = 0ull; }         \
        const float* wb = sm + OF_W3 + a_la * 36;                                 \
        const float* hb = sm + OF_H + a_eq * 4;                                   \
        _Pragma("unroll")                                                         \
        for (int mq = 0; mq < 8; ++mq) {                                          \
            float4 wq[4];                                                         \
            _Pragma("unroll")                                                     \
            for (int i = 0; i < 4; ++i) wq[i] = *(const float4*)(wb + i * (128*36) + mq * 4); \
            _Pragma("unroll")                                                     \
            for (int mm = 0; mm < 4; ++mm) {                                      \
                ulonglong2 hv = *(const ulonglong2*)(hb + (mq * 4 + mm) * 16);    \
                const float w0 = (mm==0)?wq[0].x:(mm==1)?wq[0].y:(mm==2)?wq[0].z:wq[0].w; \
                const float w1v= (mm==0)?wq[1].x:(mm==1)?wq[1].y:(mm==2)?wq[1].z:wq[1].w; \
                const float w2v= (mm==0)?wq[2].x:(mm==1)?wq[2].y:(mm==2)?wq[2].z:wq[2].w; \
                const float w3v= (mm==0)?wq[3].x:(mm==1)?wq[3].y:(mm==2)?wq[3].z:wq[3].w; \
                u64 p;                                                            \
                p = pk2(w0, w0);                                                  \
                FMA2(A_[0][0], p, hv.x, A_[0][0]); FMA2(A_[0][1], p, hv.y, A_[0][1]); \
                p = pk2(w1v, w1v);                                                \
                FMA2(A_[1][0], p, hv.x, A_[1][0]); FMA2(A_[1][1], p, hv.y, A_[1][1]); \
                p = pk2(w2v, w2v);                                                \
                FMA2(A_[2][0], p, hv.x, A_[2][0]); FMA2(A_[2][1], p, hv.y, A_[2][1]); \
                p = pk2(w3v, w3v);                                                \
                FMA2(A_[3][0], p, hv.x, A_[3][0]); FMA2(A_[3][1], p, hv.y, A_[3][1]); \
            }                                                                     \
        }                                                                         \
        _Pragma("unroll")                                                         \
        for (int i = 0; i < 4; ++i) {                                             \
            u64* dp = (u64*)(sm + OF_RW + (size_t)((HALF)*512 + a_la + 128*i) * 18 + a_eq * 4); \
            dp[0] = A_[i][0]; dp[1] = A_[i][1];                                   \
        }                                                                         \
    }

    for (int f = 0; f < 44; ++f) {
        // stage basis slice
        {
            float4* bp = (float4*)(sm + OF_BAS + tid * 8);
            bp[0] = bpre0; bp[1] = bpre1;
        }
        __syncthreads();   // S1
        if (f < 43) {
            const float* bs = bas_base + (size_t)(f + 1) * 16;
            bpre0 = __ldg((const float4*)bs);
            bpre1 = __ldg((const float4*)bs + 1);
        }

        // w3 half-0 LDG (overlapped by T-gen)
        float4 w_[8];
        #pragma unroll
        for (int i = 0; i < 8; ++i) {
            const int lr = i * 64 + s_r;
            const int o = lr >> 5, c = lr & 31;
            w_[i] = __ldg((const float4*)(w3 + ((size_t)o * 1408 + (size_t)c * 44 + f) * 32 + s_k * 4));
        }

        // T-gen: T[c][e][s] = sum_d feat*bas
        {
            u64 t[8];
            #pragma unroll
            for (int k = 0; k < 8; ++k) t[k] = 0ull;
            const char* bb = (const char*)(sm + OF_BAS + tg_e * 256);
            #pragma unroll
            for (int d = 0; d < 16; ++d) {
                u64 fp2 = pk2(fr[d], fr[d]);
                const ulonglong2* bp = (const ulonglong2*)(bb + d * 64);
                ulonglong2 q0 = bp[0], q1 = bp[1], q2 = bp[2], q3 = bp[3];
                FMA2(t[0], fp2, q0.x, t[0]); FMA2(t[1], fp2, q0.y, t[1]);
                FMA2(t[2], fp2, q1.x, t[2]); FMA2(t[3], fp2, q1.y, t[3]);
                FMA2(t[4], fp2, q2.x, t[4]); FMA2(t[5], fp2, q2.y, t[5]);
                FMA2(t[6], fp2, q3.x, t[6]); FMA2(t[7], fp2, q3.y, t[7]);
            }
            ulonglong2* tp = (ulonglong2*)(sm + OF_T + tg_c * T_CS + tg_e * T_ES);
            #pragma unroll
            for (int k = 0; k < 4; ++k) { ulonglong2 v; v.x = t[2*k]; v.y = t[2*k+1]; tp[k] = v; }
        }

        #pragma unroll
        for (int i = 0; i < 8; ++i) {
            const int lr = i * 64 + s_r;
            *(float4*)(sm + OF_W3 + lr * 36 + s_k * 4) = w_[i];
        }
        __syncthreads();   // S2: sW3 half0 + sT ready

        // prefetch half-1 w3 into regs (hidden behind A half0)
        float4 wn_[8];
        #pragma unroll
        for (int i = 0; i < 8; ++i) {
            const int gr = 512 + i * 64 + s_r;
            const int o = gr >> 5, c = gr & 31;
            wn_[i] = __ldg((const float4*)(w3 + ((size_t)o * 1408 + (size_t)c * 44 + f) * 32 + s_k * 4));
        }

        PHASE_A(0)
        __syncthreads();   // S3: rw half0 done, sW3 free

        #pragma unroll
        for (int i = 0; i < 8; ++i) {
            const int lr = i * 64 + s_r;
            *(float4*)(sm + OF_W3 + lr * 36 + s_k * 4) = wn_[i];
        }
        __syncthreads();   // S4: sW3 half1 ready

        PHASE_A(1)
        __syncthreads();   // S5: all rw ready

        // Phase B: acc[e][2o][8s] += rw[o*32+c][e] * T[c][e][8s], full c
        {
            const float* rwb = sm + OF_RW + b_e;
            const char* tb = (const char*)(sm + OF_T + b_e * T_ES + b_sh * 8);
            #pragma unroll
            for (int c = 0; c < 32; ++c) {
                float rv0 = rwb[(b_o0 * 32 + c) * 18];
                float rv1 = rwb[(b_o1 * 32 + c) * 18];
                const ulonglong2* tp = (const ulonglong2*)(tb + c * (T_CS * 4));
                ulonglong2 qa = tp[0], qb = tp[1];
                u64 rp0 = pk2(rv0, rv0), rp1 = pk2(rv1, rv1);
                FMA2(acc0[0], rp0, qa.x, acc0[0]); FMA2(acc0[1], rp0, qa.y, acc0[1]);
                FMA2(acc0[2], rp0, qb.x, acc0[2]); FMA2(acc0[3], rp0, qb.y, acc0[3]);
                FMA2(acc1[0], rp1, qa.x, acc1[0]); FMA2(acc1[1], rp1, qa.y, acc1[1]);
                FMA2(acc1[2], rp1, qb.x, acc1[2]); FMA2(acc1[3], rp1, qb.y, acc1[3]);
            }
        }
    }

    // direct store: thread owns (e, o0/o1, 8 s at b_sh*8)
    {
        float* op0 = out + (((size_t)(e0 + b_e) * 32) + b_o0) * 16 + b_sh * 8;
        float* op1 = out + (((size_t)(e0 + b_e) * 32) + b_o1) * 16 + b_sh * 8;
        ulonglong2 v;
        v.x = acc0[0]; v.y = acc0[1]; ((ulonglong2*)op0)[0] = v;
        v.x = acc0[2]; v.y = acc0[3]; ((ulonglong2*)op0)[1] = v;
        v.x = acc1[0]; v.y = acc1[1]; ((ulonglong2*)op1)[0] = v;
        v.x = acc1[2]; v.y = acc1[3]; ((ulonglong2*)op1)[1] = v;
    }
    #undef PHASE_A
}

extern "C" void kernel_launch(void* const* d_in, const int* in_sizes, int n_in,
                              void* d_out, int out_size)
{
    const float* features = (const float*)d_in[0];
    const float* inv      = (const float*)d_in[1];
    const float* basis    = (const float*)d_in[2];
    const float* w1  = (const float*)d_in[3];
    const float* b1  = (const float*)d_in[4];
    const float* g1  = (const float*)d_in[5];
    const float* be1 = (const float*)d_in[6];
    const float* w2  = (const float*)d_in[7];
    const float* b2  = (const float*)d_in[8];
    const float* g2  = (const float*)d_in[9];
    const float* be2 = (const float*)d_in[10];
    const float* w3  = (const float*)d_in[11];
    float* out = (float*)d_out;

    cudaFuncSetAttribute(conv_kernel, cudaFuncAttributeMaxDynamicSharedMemorySize,
                         SMEM_FLOATS * (int)sizeof(float));

    mlp_kernel<<<E_TOT / 8, 256>>>(inv, w1, b1, g1, be1, w2, b2, g2, be2);
    conv_kernel<<<NBLK, NTHR, SMEM_FLOATS * sizeof(float)>>>(features, basis, w3, out);
}

// round 13
// speedup vs baseline: 1.9707x; 1.0152x over previous
#include <cuda_runtime.h>
#include <cstdint>

// VersatileConvSE3  E=16384, C=O=32, D=S=16, F=44, M=32
#define E_TOT 16384
#define NE    16
#define NTHR  512
#define NBLK  (E_TOT / NE)

typedef unsigned long long u64;
#define FMA2(d,a,b,c) asm("fma.rn.f32x2 %0, %1, %2, %3;" : "=l"(d) : "l"(a), "l"(b), "l"(c))
__device__ __forceinline__ u64 pk2(float a, float b) {
    u64 r; asm("mov.b64 %0, {%1, %2};" : "=l"(r) : "f"(a), "f"(b)); return r;
}

__device__ float g_H[E_TOT * 32];

__device__ __forceinline__ float warp_sum(float v) {
    v += __shfl_xor_sync(0xffffffffu, v, 16);
    v += __shfl_xor_sync(0xffffffffu, v, 8);
    v += __shfl_xor_sync(0xffffffffu, v, 4);
    v += __shfl_xor_sync(0xffffffffu, v, 2);
    v += __shfl_xor_sync(0xffffffffu, v, 1);
    return v;
}

__global__ __launch_bounds__(256) void mlp_kernel(
    const float* __restrict__ inv,
    const float* __restrict__ w1, const float* __restrict__ b1,
    const float* __restrict__ g1, const float* __restrict__ be1,
    const float* __restrict__ w2, const float* __restrict__ b2,
    const float* __restrict__ g2, const float* __restrict__ be2)
{
    const int e = blockIdx.x * 8 + (threadIdx.x >> 5);
    const int lane = threadIdx.x & 31;
    const float* x = inv + e * 16;
    float y = b1[lane];
    #pragma unroll
    for (int d = 0; d < 16; ++d) y += x[d] * w1[lane * 16 + d];
    float mu  = warp_sum(y) * (1.0f/32.0f);
    float dz  = y - mu;
    float var = warp_sum(dz*dz) * (1.0f/32.0f);
    float h1  = fmaxf(dz * rsqrtf(var + 1e-5f) * g1[lane] + be1[lane], 0.0f);
    float y2 = b2[lane];
    #pragma unroll
    for (int m = 0; m < 32; ++m)
        y2 += __shfl_sync(0xffffffffu, h1, m) * w2[lane * 32 + m];
    mu  = warp_sum(y2) * (1.0f/32.0f);
    dz  = y2 - mu;
    var = warp_sum(dz*dz) * (1.0f/32.0f);
    g_H[e * 32 + lane] = fmaxf(dz * rsqrtf(var + 1e-5f) * g2[lane] + be2[lane], 0.0f);
}

// smem float offsets
#define OF_H    0        // [m32][e16]                       512
#define OF_BAS  512      // [e16][d16][s16]                  4096
#define OF_T    4608     // [c32: str404][sh2: str196][e16: str12][8]  12928
#define OF_RW   17536    // [row1024][20]                    20480
#define OF_W3   38016    // [lrow512][36]                    18432
#define SMEM_FLOATS 56448   // 225792 bytes
#define T_CS 404
#define T_SHS 196
#define T_ES 12

__global__ __launch_bounds__(NTHR, 1) void conv_kernel(
    const float* __restrict__ feat,
    const float* __restrict__ basis,
    const float* __restrict__ w3,
    float* __restrict__ out)
{
    extern __shared__ __align__(16) float sm[];
    const int tid = threadIdx.x;
    const int e0  = blockIdx.x * NE;

    // roles
    const int tg_e  = tid >> 5;                          // T-gen: warp = e
    const int tg_cp = (tid & 31) >> 1, tg_sh = tid & 1;  //        lane = (c-pair, s-half)
    const int s_r  = tid >> 3, s_k = tid & 7;            // w3 stager
    const int a_la = tid & 127, a_eq = tid >> 7;         // Phase A: 4 rows x 4 e
    const int b_e  = tid & 15;                           // Phase B
    const int b_og = (tid >> 4) & 15, b_sh = tid >> 8;
    const int b_o0 = b_og * 2, b_o1 = b_o0 + 1;

    // stage H transposed [m][e]
    sm[OF_H + (tid & 31) * 16 + (tid >> 5)] = g_H[(size_t)(e0 + (tid >> 5)) * 32 + (tid & 31)];

    // feat -> regs: two c rows (c = 2cp, 2cp+1) of edge tg_e
    float fr0[16], fr1[16];
    {
        const float4* fa = (const float4*)(feat + ((size_t)(e0 + tg_e) * 32 + tg_cp * 2) * 16);
        #pragma unroll
        for (int i = 0; i < 4; ++i) {
            float4 v = __ldg(fa + i);
            fr0[4*i] = v.x; fr0[4*i+1] = v.y; fr0[4*i+2] = v.z; fr0[4*i+3] = v.w;
            float4 w = __ldg(fa + 4 + i);
            fr1[4*i] = w.x; fr1[4*i+1] = w.y; fr1[4*i+2] = w.z; fr1[4*i+3] = w.w;
        }
    }

    // basis prefetch (f=0)
    const float* bas_base = basis + (((size_t)(e0 + (tid >> 5)) * 16 + ((tid >> 1) & 15)) * 44) * 16 + (tid & 1) * 8;
    float4 bpre0 = __ldg((const float4*)bas_base);
    float4 bpre1 = __ldg((const float4*)bas_base + 1);

    // Phase B persistent accumulators: 2 o x 8 s
    u64 acc0[4], acc1[4];
    #pragma unroll
    for (int k = 0; k < 4; ++k) { acc0[k] = 0ull; acc1[k] = 0ull; }

    __syncthreads();

    // Phase A: 4 rows (la+128i) x 4 e (quarter a_eq), 32 m.
    #define PHASE_A(HALF)                                                         \
    {                                                                             \
        u64 A_[4][2];                                                             \
        _Pragma("unroll")                                                         \
        for (int i = 0; i < 4; ++i) { A_[i][0] = 0ull; A_[i][1] = 0ull; }         \
        const float* wb = sm + OF_W3 + a_la * 36;                                 \
        const float* hb = sm + OF_H + a_eq * 4;                                   \
        _Pragma("unroll")                                                         \
        for (int mq = 0; mq < 8; ++mq) {                                          \
            float4 wq[4];                                                         \
            _Pragma("unroll")                                                     \
            for (int i = 0; i < 4; ++i) wq[i] = *(const float4*)(wb + i * (128*36) + mq * 4); \
            _Pragma("unroll")                                                     \
            for (int mm = 0; mm < 4; ++mm) {                                      \
                ulonglong2 hv = *(const ulonglong2*)(hb + (mq * 4 + mm) * 16);    \
                const float w0 = (mm==0)?wq[0].x:(mm==1)?wq[0].y:(mm==2)?wq[0].z:wq[0].w; \
                const float w1v= (mm==0)?wq[1].x:(mm==1)?wq[1].y:(mm==2)?wq[1].z:wq[1].w; \
                const float w2v= (mm==0)?wq[2].x:(mm==1)?wq[2].y:(mm==2)?wq[2].z:wq[2].w; \
                const float w3v= (mm==0)?wq[3].x:(mm==1)?wq[3].y:(mm==2)?wq[3].z:wq[3].w; \
                u64 p;                                                            \
                p = pk2(w0, w0);                                                  \
                FMA2(A_[0][0], p, hv.x, A_[0][0]); FMA2(A_[0][1], p, hv.y, A_[0][1]); \
                p = pk2(w1v, w1v);                                                \
                FMA2(A_[1][0], p, hv.x, A_[1][0]); FMA2(A_[1][1], p, hv.y, A_[1][1]); \
                p = pk2(w2v, w2v);                                                \
                FMA2(A_[2][0], p, hv.x, A_[2][0]); FMA2(A_[2][1], p, hv.y, A_[2][1]); \
                p = pk2(w3v, w3v);                                                \
                FMA2(A_[3][0], p, hv.x, A_[3][0]); FMA2(A_[3][1], p, hv.y, A_[3][1]); \
            }                                                                     \
        }                                                                         \
        _Pragma("unroll")                                                         \
        for (int i = 0; i < 4; ++i) {                                             \
            float* dp = sm + OF_RW + (size_t)((HALF)*512 + a_la + 128*i) * 20 + a_eq * 4; \
            ulonglong2 v; v.x = A_[i][0]; v.y = A_[i][1];                         \
            *(ulonglong2*)dp = v;                                                 \
        }                                                                         \
    }

    for (int f = 0; f < 44; ++f) {
        // stage basis slice
        {
            float4* bp = (float4*)(sm + OF_BAS + tid * 8);
            bp[0] = bpre0; bp[1] = bpre1;
        }
        __syncthreads();   // S1
        if (f < 43) {
            const float* bs = bas_base + (size_t)(f + 1) * 16;
            bpre0 = __ldg((const float4*)bs);
            bpre1 = __ldg((const float4*)bs + 1);
        }

        // w3 half-0 LDG (overlapped by T-gen)
        float4 w_[8];
        #pragma unroll
        for (int i = 0; i < 8; ++i) {
            const int lr = i * 64 + s_r;
            const int o = lr >> 5, c = lr & 31;
            w_[i] = __ldg((const float4*)(w3 + ((size_t)o * 1408 + (size_t)c * 44 + f) * 32 + s_k * 4));
        }

        // T-gen: 2 c (2cp, 2cp+1) x 8 s (half tg_sh); bas loads amortized over 2 c
        {
            u64 t0[4], t1[4];
            #pragma unroll
            for (int k = 0; k < 4; ++k) { t0[k] = 0ull; t1[k] = 0ull; }
            const float* bb = sm + OF_BAS + tg_e * 256 + tg_sh * 8;
            #pragma unroll
            for (int d = 0; d < 16; ++d) {
                ulonglong2 qa = *(const ulonglong2*)(bb + d * 16);
                ulonglong2 qb = *(const ulonglong2*)(bb + d * 16 + 4);
                u64 fa = pk2(fr0[d], fr0[d]);
                u64 fb = pk2(fr1[d], fr1[d]);
                FMA2(t0[0], fa, qa.x, t0[0]); FMA2(t0[1], fa, qa.y, t0[1]);
                FMA2(t0[2], fa, qb.x, t0[2]); FMA2(t0[3], fa, qb.y, t0[3]);
                FMA2(t1[0], fb, qa.x, t1[0]); FMA2(t1[1], fb, qa.y, t1[1]);
                FMA2(t1[2], fb, qb.x, t1[2]); FMA2(t1[3], fb, qb.y, t1[3]);
            }
            float* ta = sm + OF_T + (size_t)(tg_cp * 2) * T_CS + tg_sh * T_SHS + tg_e * T_ES;
            ulonglong2 v;
            v.x = t0[0]; v.y = t0[1]; ((ulonglong2*)ta)[0] = v;
            v.x = t0[2]; v.y = t0[3]; ((ulonglong2*)(ta + 4))[0] = v;
            v.x = t1[0]; v.y = t1[1]; ((ulonglong2*)(ta + T_CS))[0] = v;
            v.x = t1[2]; v.y = t1[3]; ((ulonglong2*)(ta + T_CS + 4))[0] = v;
        }

        #pragma unroll
        for (int i = 0; i < 8; ++i) {
            const int lr = i * 64 + s_r;
            *(float4*)(sm + OF_W3 + lr * 36 + s_k * 4) = w_[i];
        }
        __syncthreads();   // S2: sW3 half0 + sT ready

        // prefetch half-1 w3 into regs (hidden behind A half0)
        float4 wn_[8];
        #pragma unroll
        for (int i = 0; i < 8; ++i) {
            const int gr = 512 + i * 64 + s_r;
            const int o = gr >> 5, c = gr & 31;
            wn_[i] = __ldg((const float4*)(w3 + ((size_t)o * 1408 + (size_t)c * 44 + f) * 32 + s_k * 4));
        }

        PHASE_A(0)
        __syncthreads();   // S3: rw half0 done, sW3 free

        #pragma unroll
        for (int i = 0; i < 8; ++i) {
            const int lr = i * 64 + s_r;
            *(float4*)(sm + OF_W3 + lr * 36 + s_k * 4) = wn_[i];
        }
        __syncthreads();   // S4: sW3 half1 ready

        PHASE_A(1)
        __syncthreads();   // S5: all rw ready

        // Phase B: acc[e][2o][8s] += rw[o*32+c][e] * T[c][e][8s], full c
        {
            const float* rwb = sm + OF_RW + b_e;
            const float* tb  = sm + OF_T + b_sh * T_SHS + b_e * T_ES;
            #pragma unroll
            for (int c = 0; c < 32; ++c) {
                float rv0 = rwb[(b_o0 * 32 + c) * 20];
                float rv1 = rwb[(b_o1 * 32 + c) * 20];
                ulonglong2 qa = *(const ulonglong2*)(tb + c * T_CS);
                ulonglong2 qb = *(const ulonglong2*)(tb + c * T_CS + 4);
                u64 rp0 = pk2(rv0, rv0), rp1 = pk2(rv1, rv1);
                FMA2(acc0[0], rp0, qa.x, acc0[0]); FMA2(acc0[1], rp0, qa.y, acc0[1]);
                FMA2(acc0[2], rp0, qb.x, acc0[2]); FMA2(acc0[3], rp0, qb.y, acc0[3]);
                FMA2(acc1[0], rp1, qa.x, acc1[0]); FMA2(acc1[1], rp1, qa.y, acc1[1]);
                FMA2(acc1[2], rp1, qb.x, acc1[2]); FMA2(acc1[3], rp1, qb.y, acc1[3]);
            }
        }
    }

    // direct store: thread owns (e, o0/o1, 8 s at b_sh*8)
    {
        float* op0 = out + (((size_t)(e0 + b_e) * 32) + b_o0) * 16 + b_sh * 8;
        float* op1 = out + (((size_t)(e0 + b_e) * 32) + b_o1) * 16 + b_sh * 8;
        ulonglong2 v;
        v.x = acc0[0]; v.y = acc0[1]; ((ulonglong2*)op0)[0] = v;
        v.x = acc0[2]; v.y = acc0[3]; ((ulonglong2*)op0)[1] = v;
        v.x = acc1[0]; v.y = acc1[1]; ((ulonglong2*)op1)[0] = v;
        v.x = acc1[2]; v.y = acc1[3]; ((ulonglong2*)op1)[1] = v;
    }
    #undef PHASE_A
}

extern "C" void kernel_launch(void* const* d_in, const int* in_sizes, int n_in,
                              void* d_out, int out_size)
{
    const float* features = (const float*)d_in[0];
    const float* inv      = (const float*)d_in[1];
    const float* basis    = (const float*)d_in[2];
    const float* w1  = (const float*)d_in[3];
    const float* b1  = (const float*)d_in[4];
    const float* g1  = (const float*)d_in[5];
    const float* be1 = (const float*)d_in[6];
    const float* w2  = (const float*)d_in[7];
    const float* b2  = (const float*)d_in[8];
    const float* g2  = (const float*)d_in[9];
    const float* be2 = (const float*)d_in[10];
    const float* w3  = (const float*)d_in[11];
    float* out = (float*)d_out;

    cudaFuncSetAttribute(conv_kernel, cudaFuncAttributeMaxDynamicSharedMemorySize,
                         SMEM_FLOATS * (int)sizeof(float));

    mlp_kernel<<<E_TOT / 8, 256>>>(inv, w1, b1, g1, be1, w2, b2, g2, be2);
    conv_kernel<<<NBLK, NTHR, SMEM_FLOATS * sizeof(float)>>>(features, basis, w3, out);
}

// round 14
// speedup vs baseline: 2.0021x; 1.0159x over previous
#include <cuda_runtime.h>
#include <cstdint>

// VersatileConvSE3  E=16384, C=O=32, D=S=16, F=44, M=32
#define E_TOT 16384
#define NE    16
#define NTHR  512
#define NBLK  (E_TOT / NE)

typedef unsigned long long u64;
#define FMA2(d,a,b,c) asm("fma.rn.f32x2 %0, %1, %2, %3;" : "=l"(d) : "l"(a), "l"(b), "l"(c))
__device__ __forceinline__ u64 pk2(float a, float b) {
    u64 r; asm("mov.b64 %0, {%1, %2};" : "=l"(r) : "f"(a), "f"(b)); return r;
}

__device__ float g_H[E_TOT * 32];

__device__ __forceinline__ float warp_sum(float v) {
    v += __shfl_xor_sync(0xffffffffu, v, 16);
    v += __shfl_xor_sync(0xffffffffu, v, 8);
    v += __shfl_xor_sync(0xffffffffu, v, 4);
    v += __shfl_xor_sync(0xffffffffu, v, 2);
    v += __shfl_xor_sync(0xffffffffu, v, 1);
    return v;
}

__global__ __launch_bounds__(256) void mlp_kernel(
    const float* __restrict__ inv,
    const float* __restrict__ w1, const float* __restrict__ b1,
    const float* __restrict__ g1, const float* __restrict__ be1,
    const float* __restrict__ w2, const float* __restrict__ b2,
    const float* __restrict__ g2, const float* __restrict__ be2)
{
    const int e = blockIdx.x * 8 + (threadIdx.x >> 5);
    const int lane = threadIdx.x & 31;
    const float* x = inv + e * 16;
    float y = b1[lane];
    #pragma unroll
    for (int d = 0; d < 16; ++d) y += x[d] * w1[lane * 16 + d];
    float mu  = warp_sum(y) * (1.0f/32.0f);
    float dz  = y - mu;
    float var = warp_sum(dz*dz) * (1.0f/32.0f);
    float h1  = fmaxf(dz * rsqrtf(var + 1e-5f) * g1[lane] + be1[lane], 0.0f);
    float y2 = b2[lane];
    #pragma unroll
    for (int m = 0; m < 32; ++m)
        y2 += __shfl_sync(0xffffffffu, h1, m) * w2[lane * 32 + m];
    mu  = warp_sum(y2) * (1.0f/32.0f);
    dz  = y2 - mu;
    var = warp_sum(dz*dz) * (1.0f/32.0f);
    g_H[e * 32 + lane] = fmaxf(dz * rsqrtf(var + 1e-5f) * g2[lane] + be2[lane], 0.0f);
}

// smem float offsets
#define OF_H    0        // [m32][e16]                       512
#define OF_BAS  512      // [e16][d16][s16]                  4096
#define OF_T    4608     // [c32: str404][sh2: str196][e16: str12][8]  12928
#define OF_RW   17536    // [row1024][20]                    20480
#define OF_W3   38016    // [lrow512][36]                    18432
#define SMEM_FLOATS 56448   // 225792 bytes
#define T_CS 404
#define T_SHS 196
#define T_ES 12

__global__ __launch_bounds__(NTHR, 1) void conv_kernel(
    const float* __restrict__ feat,
    const float* __restrict__ basis,
    const float* __restrict__ w3,
    float* __restrict__ out)
{
    extern __shared__ __align__(16) float sm[];
    const int tid = threadIdx.x;
    const int e0  = blockIdx.x * NE;

    // roles
    const int tg_e  = tid >> 5;                          // T-gen: warp = e
    const int tg_cp = (tid & 31) >> 1, tg_sh = tid & 1;  //        lane = (c-pair, s-half)
    const int s_r  = tid >> 3, s_k = tid & 7;            // w3 stager
    const int a_r0 = tid & 255, a_eh = tid >> 8;         // Phase A: 2 rows x 8 e
    const int b_e  = tid & 15;                           // Phase B
    const int b_og = (tid >> 4) & 15, b_sh = tid >> 8;
    const int b_o0 = b_og * 2, b_o1 = b_o0 + 1;

    // stage H transposed [m][e]
    sm[OF_H + (tid & 31) * 16 + (tid >> 5)] = g_H[(size_t)(e0 + (tid >> 5)) * 32 + (tid & 31)];

    // feat -> regs: two c rows (c = 2cp, 2cp+1) of edge tg_e
    float fr0[16], fr1[16];
    {
        const float4* fa = (const float4*)(feat + ((size_t)(e0 + tg_e) * 32 + tg_cp * 2) * 16);
        #pragma unroll
        for (int i = 0; i < 4; ++i) {
            float4 v = __ldg(fa + i);
            fr0[4*i] = v.x; fr0[4*i+1] = v.y; fr0[4*i+2] = v.z; fr0[4*i+3] = v.w;
            float4 w = __ldg(fa + 4 + i);
            fr1[4*i] = w.x; fr1[4*i+1] = w.y; fr1[4*i+2] = w.z; fr1[4*i+3] = w.w;
        }
    }

    // basis prefetch (f=0)
    const float* bas_base = basis + (((size_t)(e0 + (tid >> 5)) * 16 + ((tid >> 1) & 15)) * 44) * 16 + (tid & 1) * 8;
    float4 bpre0 = __ldg((const float4*)bas_base);
    float4 bpre1 = __ldg((const float4*)bas_base + 1);

    // Phase B persistent accumulators: 2 o x 8 s
    u64 acc0[4], acc1[4];
    #pragma unroll
    for (int k = 0; k < 4; ++k) { acc0[k] = 0ull; acc1[k] = 0ull; }

    __syncthreads();

    // Phase A: 2 rows (r0, r0+256) x 8 e (half a_eh), 32 m.
    // w loads: 2 .128 per mq (half the bytes of the 4-row tile);
    // h loads: warp-uniform broadcast .128 (1 cyc each).
    #define PHASE_A(HALF)                                                         \
    {                                                                             \
        u64 A_[2][4];                                                             \
        _Pragma("unroll")                                                         \
        for (int i = 0; i < 2; ++i) { A_[i][0]=0ull; A_[i][1]=0ull; A_[i][2]=0ull; A_[i][3]=0ull; } \
        const float* wb0 = sm + OF_W3 + a_r0 * 36;                                \
        const float* wb1 = sm + OF_W3 + (a_r0 + 256) * 36;                        \
        const float* hb  = sm + OF_H + a_eh * 8;                                  \
        _Pragma("unroll")                                                         \
        for (int mq = 0; mq < 8; ++mq) {                                          \
            float4 w0q = *(const float4*)(wb0 + mq * 4);                          \
            float4 w1q = *(const float4*)(wb1 + mq * 4);                          \
            _Pragma("unroll")                                                     \
            for (int mm = 0; mm < 4; ++mm) {                                      \
                const int m = mq * 4 + mm;                                        \
                ulonglong2 ha = *(const ulonglong2*)(hb + m * 16);                \
                ulonglong2 hc = *(const ulonglong2*)(hb + m * 16 + 4);            \
                const float w0 = (mm==0)?w0q.x:(mm==1)?w0q.y:(mm==2)?w0q.z:w0q.w; \
                const float w1v= (mm==0)?w1q.x:(mm==1)?w1q.y:(mm==2)?w1q.z:w1q.w; \
                u64 p0 = pk2(w0, w0), p1 = pk2(w1v, w1v);                         \
                FMA2(A_[0][0], p0, ha.x, A_[0][0]); FMA2(A_[0][1], p0, ha.y, A_[0][1]); \
                FMA2(A_[0][2], p0, hc.x, A_[0][2]); FMA2(A_[0][3], p0, hc.y, A_[0][3]); \
                FMA2(A_[1][0], p1, ha.x, A_[1][0]); FMA2(A_[1][1], p1, ha.y, A_[1][1]); \
                FMA2(A_[1][2], p1, hc.x, A_[1][2]); FMA2(A_[1][3], p1, hc.y, A_[1][3]); \
            }                                                                     \
        }                                                                         \
        float* dp0 = sm + OF_RW + (size_t)((HALF)*512 + a_r0) * 20 + a_eh * 8;    \
        float* dp1 = sm + OF_RW + (size_t)((HALF)*512 + a_r0 + 256) * 20 + a_eh * 8; \
        ulonglong2 v;                                                             \
        v.x = A_[0][0]; v.y = A_[0][1]; ((ulonglong2*)dp0)[0] = v;                \
        v.x = A_[0][2]; v.y = A_[0][3]; ((ulonglong2*)(dp0 + 4))[0] = v;          \
        v.x = A_[1][0]; v.y = A_[1][1]; ((ulonglong2*)dp1)[0] = v;                \
        v.x = A_[1][2]; v.y = A_[1][3]; ((ulonglong2*)(dp1 + 4))[0] = v;          \
    }

    for (int f = 0; f < 44; ++f) {
        // stage basis slice
        {
            float4* bp = (float4*)(sm + OF_BAS + tid * 8);
            bp[0] = bpre0; bp[1] = bpre1;
        }
        __syncthreads();   // S1
        if (f < 43) {
            const float* bs = bas_base + (size_t)(f + 1) * 16;
            bpre0 = __ldg((const float4*)bs);
            bpre1 = __ldg((const float4*)bs + 1);
        }

        // w3 half-0 LDG (overlapped by T-gen)
        float4 w_[8];
        #pragma unroll
        for (int i = 0; i < 8; ++i) {
            const int lr = i * 64 + s_r;
            const int o = lr >> 5, c = lr & 31;
            w_[i] = __ldg((const float4*)(w3 + ((size_t)o * 1408 + (size_t)c * 44 + f) * 32 + s_k * 4));
        }

        // T-gen: 2 c (2cp, 2cp+1) x 8 s (half tg_sh)
        {
            u64 t0[4], t1[4];
            #pragma unroll
            for (int k = 0; k < 4; ++k) { t0[k] = 0ull; t1[k] = 0ull; }
            const float* bb = sm + OF_BAS + tg_e * 256 + tg_sh * 8;
            #pragma unroll
            for (int d = 0; d < 16; ++d) {
                ulonglong2 qa = *(const ulonglong2*)(bb + d * 16);
                ulonglong2 qb = *(const ulonglong2*)(bb + d * 16 + 4);
                u64 fa = pk2(fr0[d], fr0[d]);
                u64 fb = pk2(fr1[d], fr1[d]);
                FMA2(t0[0], fa, qa.x, t0[0]); FMA2(t0[1], fa, qa.y, t0[1]);
                FMA2(t0[2], fa, qb.x, t0[2]); FMA2(t0[3], fa, qb.y, t0[3]);
                FMA2(t1[0], fb, qa.x, t1[0]); FMA2(t1[1], fb, qa.y, t1[1]);
                FMA2(t1[2], fb, qb.x, t1[2]); FMA2(t1[3], fb, qb.y, t1[3]);
            }
            float* ta = sm + OF_T + (size_t)(tg_cp * 2) * T_CS + tg_sh * T_SHS + tg_e * T_ES;
            ulonglong2 v;
            v.x = t0[0]; v.y = t0[1]; ((ulonglong2*)ta)[0] = v;
            v.x = t0[2]; v.y = t0[3]; ((ulonglong2*)(ta + 4))[0] = v;
            v.x = t1[0]; v.y = t1[1]; ((ulonglong2*)(ta + T_CS))[0] = v;
            v.x = t1[2]; v.y = t1[3]; ((ulonglong2*)(ta + T_CS + 4))[0] = v;
        }

        #pragma unroll
        for (int i = 0; i < 8; ++i) {
            const int lr = i * 64 + s_r;
            *(float4*)(sm + OF_W3 + lr * 36 + s_k * 4) = w_[i];
        }
        __syncthreads();   // S2: sW3 half0 + sT ready

        // prefetch half-1 w3 into regs (hidden behind A half0)
        float4 wn_[8];
        #pragma unroll
        for (int i = 0; i < 8; ++i) {
            const int gr = 512 + i * 64 + s_r;
            const int o = gr >> 5, c = gr & 31;
            wn_[i] = __ldg((const float4*)(w3 + ((size_t)o * 1408 + (size_t)c * 44 + f) * 32 + s_k * 4));
        }

        PHASE_A(0)
        __syncthreads();   // S3: rw half0 done, sW3 free

        #pragma unroll
        for (int i = 0; i < 8; ++i) {
            const int lr = i * 64 + s_r;
            *(float4*)(sm + OF_W3 + lr * 36 + s_k * 4) = wn_[i];
        }
        __syncthreads();   // S4: sW3 half1 ready

        PHASE_A(1)
        __syncthreads();   // S5: all rw ready

        // Phase B: acc[e][2o][8s] += rw[o*32+c][e] * T[c][e][8s], full c
        {
            const float* rwb = sm + OF_RW + b_e;
            const float* tb  = sm + OF_T + b_sh * T_SHS + b_e * T_ES;
            #pragma unroll
            for (int c = 0; c < 32; ++c) {
                float rv0 = rwb[(b_o0 * 32 + c) * 20];
                float rv1 = rwb[(b_o1 * 32 + c) * 20];
                ulonglong2 qa = *(const ulonglong2*)(tb + c * T_CS);
                ulonglong2 qb = *(const ulonglong2*)(tb + c * T_CS + 4);
                u64 rp0 = pk2(rv0, rv0), rp1 = pk2(rv1, rv1);
                FMA2(acc0[0], rp0, qa.x, acc0[0]); FMA2(acc0[1], rp0, qa.y, acc0[1]);
                FMA2(acc0[2], rp0, qb.x, acc0[2]); FMA2(acc0[3], rp0, qb.y, acc0[3]);
                FMA2(acc1[0], rp1, qa.x, acc1[0]); FMA2(acc1[1], rp1, qa.y, acc1[1]);
                FMA2(acc1[2], rp1, qb.x, acc1[2]); FMA2(acc1[3], rp1, qb.y, acc1[3]);
            }
        }
    }

    // direct store: thread owns (e, o0/o1, 8 s at b_sh*8)
    {
        float* op0 = out + (((size_t)(e0 + b_e) * 32) + b_o0) * 16 + b_sh * 8;
        float* op1 = out + (((size_t)(e0 + b_e) * 32) + b_o1) * 16 + b_sh * 8;
        ulonglong2 v;
        v.x = acc0[0]; v.y = acc0[1]; ((ulonglong2*)op0)[0] = v;
        v.x = acc0[2]; v.y = acc0[3]; ((ulonglong2*)op0)[1] = v;
        v.x = acc1[0]; v.y = acc1[1]; ((ulonglong2*)op1)[0] = v;
        v.x = acc1[2]; v.y = acc1[3]; ((ulonglong2*)op1)[1] = v;
    }
    #undef PHASE_A
}

extern "C" void kernel_launch(void* const* d_in, const int* in_sizes, int n_in,
                              void* d_out, int out_size)
{
    const float* features = (const float*)d_in[0];
    const float* inv      = (const float*)d_in[1];
    const float* basis    = (const float*)d_in[2];
    const float* w1  = (const float*)d_in[3];
    const float* b1  = (const float*)d_in[4];
    const float* g1  = (const float*)d_in[5];
    const float* be1 = (const float*)d_in[6];
    const float* w2  = (const float*)d_in[7];
    const float* b2  = (const float*)d_in[8];
    const float* g2  = (const float*)d_in[9];
    const float* be2 = (const float*)d_in[10];
    const float* w3  = (const float*)d_in[11];
    float* out = (float*)d_out;

    cudaFuncSetAttribute(conv_kernel, cudaFuncAttributeMaxDynamicSharedMemorySize,
                         SMEM_FLOATS * (int)sizeof(float));

    mlp_kernel<<<E_TOT / 8, 256>>>(inv, w1, b1, g1, be1, w2, b2, g2, be2);
    conv_kernel<<<NBLK, NTHR, SMEM_FLOATS * sizeof(float)>>>(features, basis, w3, out);
}

// round 15
// speedup vs baseline: 2.2478x; 1.1227x over previous
#include <cuda_runtime.h>
#include <cstdint>

// VersatileConvSE3  E=16384, C=O=32, D=S=16, F=44, M=32
#define E_TOT 16384
#define NE    16
#define NTHR  512
#define NBLK  (E_TOT / NE)

typedef unsigned long long u64;
#define FMA2(d,a,b,c) asm("fma.rn.f32x2 %0, %1, %2, %3;" : "=l"(d) : "l"(a), "l"(b), "l"(c))
__device__ __forceinline__ u64 pk2(float a, float b) {
    u64 r; asm("mov.b64 %0, {%1, %2};" : "=l"(r) : "f"(a), "f"(b)); return r;
}

__device__ float g_H[E_TOT * 32];

__device__ __forceinline__ float warp_sum(float v) {
    v += __shfl_xor_sync(0xffffffffu, v, 16);
    v += __shfl_xor_sync(0xffffffffu, v, 8);
    v += __shfl_xor_sync(0xffffffffu, v, 4);
    v += __shfl_xor_sync(0xffffffffu, v, 2);
    v += __shfl_xor_sync(0xffffffffu, v, 1);
    return v;
}

__global__ __launch_bounds__(256) void mlp_kernel(
    const float* __restrict__ inv,
    const float* __restrict__ w1, const float* __restrict__ b1,
    const float* __restrict__ g1, const float* __restrict__ be1,
    const float* __restrict__ w2, const float* __restrict__ b2,
    const float* __restrict__ g2, const float* __restrict__ be2)
{
    const int e = blockIdx.x * 8 + (threadIdx.x >> 5);
    const int lane = threadIdx.x & 31;
    const float* x = inv + e * 16;
    float y = b1[lane];
    #pragma unroll
    for (int d = 0; d < 16; ++d) y += x[d] * w1[lane * 16 + d];
    float mu  = warp_sum(y) * (1.0f/32.0f);
    float dz  = y - mu;
    float var = warp_sum(dz*dz) * (1.0f/32.0f);
    float h1  = fmaxf(dz * rsqrtf(var + 1e-5f) * g1[lane] + be1[lane], 0.0f);
    float y2 = b2[lane];
    #pragma unroll
    for (int m = 0; m < 32; ++m)
        y2 += __shfl_sync(0xffffffffu, h1, m) * w2[lane * 32 + m];
    mu  = warp_sum(y2) * (1.0f/32.0f);
    dz  = y2 - mu;
    var = warp_sum(dz*dz) * (1.0f/32.0f);
    g_H[e * 32 + lane] = fmaxf(dz * rsqrtf(var + 1e-5f) * g2[lane] + be2[lane], 0.0f);
}

// smem float offsets
#define OF_H    0        // [m32][e16]                       512
#define OF_BAS  512      // [e16][d16][s16]                  4096
#define OF_T    4608     // [c32: str404][sh2: str196][e16: str12][8]  12928
#define OF_RW   17536    // o-major: o*578 + c*18 + e        18496
#define OF_W3   36032    // [lrow512][36]                    18432
#define SMEM_FLOATS 54464   // 217856 bytes
#define T_CS 404
#define T_SHS 196
#define T_ES 12
#define RW_OS 578
#define RW_CS 18

__global__ __launch_bounds__(NTHR, 1) void conv_kernel(
    const float* __restrict__ feat,
    const float* __restrict__ basis,
    const float* __restrict__ w3,
    float* __restrict__ out)
{
    extern __shared__ __align__(16) float sm[];
    const int tid = threadIdx.x;
    const int e0  = blockIdx.x * NE;

    // roles
    const int tg_e  = tid >> 5;                          // T-gen: warp = e
    const int tg_cp = (tid & 31) >> 1, tg_sh = tid & 1;  //        lane = (c-pair, s-half)
    const int s_r  = tid >> 3, s_k = tid & 7;            // w3 stager
    const int a_r0 = tid & 255, a_eh = tid >> 8;         // Phase A: 2 rows x 8 e
    // Phase B lane map: lane = og_lo(3b) x e_lo(2b); warp = og_hi, e_hi, sh
    const int b_lane = tid & 31, b_w = tid >> 5;
    const int b_og = (b_lane & 7) | ((b_w & 1) << 3);
    const int b_e  = (b_lane >> 3) | (((b_w >> 1) & 3) << 2);
    const int b_sh = b_w >> 3;
    const int b_o0 = b_og * 2, b_o1 = b_o0 + 1;

    // stage H transposed [m][e]
    sm[OF_H + (tid & 31) * 16 + (tid >> 5)] = g_H[(size_t)(e0 + (tid >> 5)) * 32 + (tid & 31)];

    // feat -> regs: two c rows (c = 2cp, 2cp+1) of edge tg_e
    float fr0[16], fr1[16];
    {
        const float4* fa = (const float4*)(feat + ((size_t)(e0 + tg_e) * 32 + tg_cp * 2) * 16);
        #pragma unroll
        for (int i = 0; i < 4; ++i) {
            float4 v = __ldg(fa + i);
            fr0[4*i] = v.x; fr0[4*i+1] = v.y; fr0[4*i+2] = v.z; fr0[4*i+3] = v.w;
            float4 w = __ldg(fa + 4 + i);
            fr1[4*i] = w.x; fr1[4*i+1] = w.y; fr1[4*i+2] = w.z; fr1[4*i+3] = w.w;
        }
    }

    // basis prefetch (f=0)
    const float* bas_base = basis + (((size_t)(e0 + (tid >> 5)) * 16 + ((tid >> 1) & 15)) * 44) * 16 + (tid & 1) * 8;
    float4 bpre0 = __ldg((const float4*)bas_base);
    float4 bpre1 = __ldg((const float4*)bas_base + 1);

    // Phase B persistent accumulators: 2 o x 8 s
    u64 acc0[4], acc1[4];
    #pragma unroll
    for (int k = 0; k < 4; ++k) { acc0[k] = 0ull; acc1[k] = 0ull; }

    __syncthreads();

    // Phase A: 2 rows (r0, r0+256) x 8 e (half a_eh), 32 m.
    // rw stored o-major: o*RW_OS + c*RW_CS + e  (4x .64 per row)
    #define PHASE_A(HALF)                                                         \
    {                                                                             \
        u64 A_[2][4];                                                             \
        _Pragma("unroll")                                                         \
        for (int i = 0; i < 2; ++i) { A_[i][0]=0ull; A_[i][1]=0ull; A_[i][2]=0ull; A_[i][3]=0ull; } \
        const float* wb0 = sm + OF_W3 + a_r0 * 36;                                \
        const float* wb1 = sm + OF_W3 + (a_r0 + 256) * 36;                        \
        const float* hb  = sm + OF_H + a_eh * 8;                                  \
        _Pragma("unroll")                                                         \
        for (int mq = 0; mq < 8; ++mq) {                                          \
            float4 w0q = *(const float4*)(wb0 + mq * 4);                          \
            float4 w1q = *(const float4*)(wb1 + mq * 4);                          \
            _Pragma("unroll")                                                     \
            for (int mm = 0; mm < 4; ++mm) {                                      \
                const int m = mq * 4 + mm;                                        \
                ulonglong2 ha = *(const ulonglong2*)(hb + m * 16);                \
                ulonglong2 hc = *(const ulonglong2*)(hb + m * 16 + 4);            \
                const float w0 = (mm==0)?w0q.x:(mm==1)?w0q.y:(mm==2)?w0q.z:w0q.w; \
                const float w1v= (mm==0)?w1q.x:(mm==1)?w1q.y:(mm==2)?w1q.z:w1q.w; \
                u64 p0 = pk2(w0, w0), p1 = pk2(w1v, w1v);                         \
                FMA2(A_[0][0], p0, ha.x, A_[0][0]); FMA2(A_[0][1], p0, ha.y, A_[0][1]); \
                FMA2(A_[0][2], p0, hc.x, A_[0][2]); FMA2(A_[0][3], p0, hc.y, A_[0][3]); \
                FMA2(A_[1][0], p1, ha.x, A_[1][0]); FMA2(A_[1][1], p1, ha.y, A_[1][1]); \
                FMA2(A_[1][2], p1, hc.x, A_[1][2]); FMA2(A_[1][3], p1, hc.y, A_[1][3]); \
            }                                                                     \
        }                                                                         \
        _Pragma("unroll")                                                         \
        for (int i = 0; i < 2; ++i) {                                             \
            const int gr = (HALF) * 512 + a_r0 + 256 * i;                         \
            const int o = gr >> 5, c = gr & 31;                                   \
            u64* dp = (u64*)(sm + OF_RW + o * RW_OS + c * RW_CS + a_eh * 8);      \
            dp[0] = A_[i][0]; dp[1] = A_[i][1];                                   \
            dp[2] = A_[i][2]; dp[3] = A_[i][3];                                   \
        }                                                                         \
    }

    for (int f = 0; f < 44; ++f) {
        // stage basis slice
        {
            float4* bp = (float4*)(sm + OF_BAS + tid * 8);
            bp[0] = bpre0; bp[1] = bpre1;
        }
        __syncthreads();   // S1
        if (f < 43) {
            const float* bs = bas_base + (size_t)(f + 1) * 16;
            bpre0 = __ldg((const float4*)bs);
            bpre1 = __ldg((const float4*)bs + 1);
        }

        // w3 half-0 LDG (overlapped by T-gen)
        float4 w_[8];
        #pragma unroll
        for (int i = 0; i < 8; ++i) {
            const int lr = i * 64 + s_r;
            const int o = lr >> 5, c = lr & 31;
            w_[i] = __ldg((const float4*)(w3 + ((size_t)o * 1408 + (size_t)c * 44 + f) * 32 + s_k * 4));
        }

        // T-gen: 2 c (2cp, 2cp+1) x 8 s (half tg_sh)
        {
            u64 t0[4], t1[4];
            #pragma unroll
            for (int k = 0; k < 4; ++k) { t0[k] = 0ull; t1[k] = 0ull; }
            const float* bb = sm + OF_BAS + tg_e * 256 + tg_sh * 8;
            #pragma unroll
            for (int d = 0; d < 16; ++d) {
                ulonglong2 qa = *(const ulonglong2*)(bb + d * 16);
                ulonglong2 qb = *(const ulonglong2*)(bb + d * 16 + 4);
                u64 fa = pk2(fr0[d], fr0[d]);
                u64 fb = pk2(fr1[d], fr1[d]);
                FMA2(t0[0], fa, qa.x, t0[0]); FMA2(t0[1], fa, qa.y, t0[1]);
                FMA2(t0[2], fa, qb.x, t0[2]); FMA2(t0[3], fa, qb.y, t0[3]);
                FMA2(t1[0], fb, qa.x, t1[0]); FMA2(t1[1], fb, qa.y, t1[1]);
                FMA2(t1[2], fb, qb.x, t1[2]); FMA2(t1[3], fb, qb.y, t1[3]);
            }
            float* ta = sm + OF_T + (size_t)(tg_cp * 2) * T_CS + tg_sh * T_SHS + tg_e * T_ES;
            ulonglong2 v;
            v.x = t0[0]; v.y = t0[1]; ((ulonglong2*)ta)[0] = v;
            v.x = t0[2]; v.y = t0[3]; ((ulonglong2*)(ta + 4))[0] = v;
            v.x = t1[0]; v.y = t1[1]; ((ulonglong2*)(ta + T_CS))[0] = v;
            v.x = t1[2]; v.y = t1[3]; ((ulonglong2*)(ta + T_CS + 4))[0] = v;
        }

        #pragma unroll
        for (int i = 0; i < 8; ++i) {
            const int lr = i * 64 + s_r;
            *(float4*)(sm + OF_W3 + lr * 36 + s_k * 4) = w_[i];
        }
        __syncthreads();   // S2: sW3 half0 + sT ready

        // prefetch half-1 w3 into regs (hidden behind A half0)
        float4 wn_[8];
        #pragma unroll
        for (int i = 0; i < 8; ++i) {
            const int gr = 512 + i * 64 + s_r;
            const int o = gr >> 5, c = gr & 31;
            wn_[i] = __ldg((const float4*)(w3 + ((size_t)o * 1408 + (size_t)c * 44 + f) * 32 + s_k * 4));
        }

        PHASE_A(0)
        __syncthreads();   // S3: rw half0 done, sW3 free

        #pragma unroll
        for (int i = 0; i < 8; ++i) {
            const int lr = i * 64 + s_r;
            *(float4*)(sm + OF_W3 + lr * 36 + s_k * 4) = wn_[i];
        }
        __syncthreads();   // S4: sW3 half1 ready

        PHASE_A(1)
        __syncthreads();   // S5: all rw ready

        // Phase B: acc[e][2o][8s] += rw[o][c][e] * T[c][e][8s], full c
        {
            const float* rwb = sm + OF_RW + b_e;
            const float* tb  = sm + OF_T + b_sh * T_SHS + b_e * T_ES;
            #pragma unroll
            for (int c = 0; c < 32; ++c) {
                float rv0 = rwb[b_o0 * RW_OS + c * RW_CS];
                float rv1 = rwb[b_o1 * RW_OS + c * RW_CS];
                ulonglong2 qa = *(const ulonglong2*)(tb + c * T_CS);
                ulonglong2 qb = *(const ulonglong2*)(tb + c * T_CS + 4);
                u64 rp0 = pk2(rv0, rv0), rp1 = pk2(rv1, rv1);
                FMA2(acc0[0], rp0, qa.x, acc0[0]); FMA2(acc0[1], rp0, qa.y, acc0[1]);
                FMA2(acc0[2], rp0, qb.x, acc0[2]); FMA2(acc0[3], rp0, qb.y, acc0[3]);
                FMA2(acc1[0], rp1, qa.x, acc1[0]); FMA2(acc1[1], rp1, qa.y, acc1[1]);
                FMA2(acc1[2], rp1, qb.x, acc1[2]); FMA2(acc1[3], rp1, qb.y, acc1[3]);
            }
        }
    }

    // direct store: thread owns (e, o0/o1, 8 s at b_sh*8)
    {
        float* op0 = out + (((size_t)(e0 + b_e) * 32) + b_o0) * 16 + b_sh * 8;
        float* op1 = out + (((size_t)(e0 + b_e) * 32) + b_o1) * 16 + b_sh * 8;
        ulonglong2 v;
        v.x = acc0[0]; v.y = acc0[1]; ((ulonglong2*)op0)[0] = v;
        v.x = acc0[2]; v.y = acc0[3]; ((ulonglong2*)op0)[1] = v;
        v.x = acc1[0]; v.y = acc1[1]; ((ulonglong2*)op1)[0] = v;
        v.x = acc1[2]; v.y = acc1[3]; ((ulonglong2*)op1)[1] = v;
    }
    #undef PHASE_A
}

extern "C" void kernel_launch(void* const* d_in, const int* in_sizes, int n_in,
                              void* d_out, int out_size)
{
    const float* features = (const float*)d_in[0];
    const float* inv      = (const float*)d_in[1];
    const float* basis    = (const float*)d_in[2];
    const float* w1  = (const float*)d_in[3];
    const float* b1  = (const float*)d_in[4];
    const float* g1  = (const float*)d_in[5];
    const float* be1 = (const float*)d_in[6];
    const float* w2  = (const float*)d_in[7];
    const float* b2  = (const float*)d_in[8];
    const float* g2  = (const float*)d_in[9];
    const float* be2 = (const float*)d_in[10];
    const float* w3  = (const float*)d_in[11];
    float* out = (float*)d_out;

    cudaFuncSetAttribute(conv_kernel, cudaFuncAttributeMaxDynamicSharedMemorySize,
                         SMEM_FLOATS * (int)sizeof(float));

    mlp_kernel<<<E_TOT / 8, 256>>>(inv, w1, b1, g1, be1, w2, b2, g2, be2);
    conv_kernel<<<NBLK, NTHR, SMEM_FLOATS * sizeof(float)>>>(features, basis, w3, out);
}